// round 1
// baseline (speedup 1.0000x reference)
#include <cuda_runtime.h>

// Problem constants (fixed by the reference)
#define E_EDGES   2000000
#define NSEG      100000
#define INV_TEMP  0.125f   // 1 / TEMPERATURE, TEMPERATURE = 8.0

// Scratch: per-segment softmax denominators. __device__ global (no allocs allowed).
__device__ float g_sum[NSEG];

// ---------------------------------------------------------------------------
// Index dtype detection: JAX reference requests int64, but default JAX config
// (x64 disabled) canonicalizes to int32. Detect at runtime:
//   Read the 8 bytes at int64-element position E/4.
//   - If buffer is int64: (lo = value ~25000, hi = 0)        -> .y == 0
//   - If buffer is int32: (int32[E/2] ~50000, int32[E/2+1])  -> .y != 0
// Sorted uniform over [0,100000) guarantees the mid-buffer value is nonzero.
// One broadcast, fully cached load per thread — negligible.
// ---------------------------------------------------------------------------
__device__ __forceinline__ bool index_is_64(const void* __restrict__ idx) {
    const int2 probe = __ldg(&((const int2*)idx)[E_EDGES / 4]);
    return probe.y == 0;
}

__device__ __forceinline__ int idx_at(const void* __restrict__ idx, bool is64, int i) {
    if (is64) return (int)__ldg(&((const long long*)idx)[i]);
    else      return __ldg(&((const int*)idx)[i]);
}

// ---------------------------------------------------------------------------
// K0: zero the denominators (must run every launch; graph-capturable).
// ---------------------------------------------------------------------------
__global__ void init_sum_kernel() {
    int i = blockIdx.x * blockDim.x + threadIdx.x;
    if (i < NSEG) g_sum[i] = 0.0f;
}

// ---------------------------------------------------------------------------
// K1: per-edge dot product -> exp -> store numerator, accumulate denominator.
// Half-warp (16 lanes) per edge; each lane loads one float4 from q and k
// (16 lanes x 16B = 256B = one full row, perfectly coalesced).
// ---------------------------------------------------------------------------
__global__ void __launch_bounds__(256)
score_exp_kernel(const float4* __restrict__ q,
                 const float4* __restrict__ k,
                 const void*   __restrict__ index,
                 float*        __restrict__ out) {
    const int tid  = blockIdx.x * blockDim.x + threadIdx.x;
    const int warp = tid >> 5;
    const int lane = tid & 31;
    const int half = lane >> 4;       // which edge within the warp
    const int sub  = lane & 15;       // lane within the 16-lane group

    const long long e = (long long)warp * 2 + half;
    if (e >= E_EDGES) return;

    const bool is64 = index_is_64(index);

    // Row e = 64 floats = 16 float4
    const float4 a = __ldg(&q[e * 16 + sub]);
    const float4 b = __ldg(&k[e * 16 + sub]);
    float d = a.x * b.x + a.y * b.y + a.z * b.z + a.w * b.w;

    // Reduce across the 16-lane group (xor offsets stay inside the group)
    d += __shfl_xor_sync(0xFFFFFFFFu, d, 8);
    d += __shfl_xor_sync(0xFFFFFFFFu, d, 4);
    d += __shfl_xor_sync(0xFFFFFFFFu, d, 2);
    d += __shfl_xor_sync(0xFFFFFFFFu, d, 1);

    if (sub == 0) {
        const float ex = __expf(d * INV_TEMP);
        out[e] = ex;
        const int seg = idx_at(index, is64, (int)e);
        atomicAdd(&g_sum[seg], ex);   // no return value used -> REDG
    }
}

// ---------------------------------------------------------------------------
// K2: normalize. 4 edges per thread (E divisible by 4), vectorized out access.
// Sorted index -> segment-sum gathers hit L2/L1.
// ---------------------------------------------------------------------------
__global__ void __launch_bounds__(256)
normalize_kernel(const void* __restrict__ index,
                 float*      __restrict__ out) {
    const int t = blockIdx.x * blockDim.x + threadIdx.x;
    const int i = t * 4;
    if (i >= E_EDGES) return;

    const bool is64 = index_is_64(index);

    float4 o = *reinterpret_cast<float4*>(out + i);
    o.x /= g_sum[idx_at(index, is64, i + 0)];
    o.y /= g_sum[idx_at(index, is64, i + 1)];
    o.z /= g_sum[idx_at(index, is64, i + 2)];
    o.w /= g_sum[idx_at(index, is64, i + 3)];
    *reinterpret_cast<float4*>(out + i) = o;
}

// ---------------------------------------------------------------------------
// Launch: inputs in metadata order: q [E*64 f32], k [E*64 f32], index [E].
// Output: E f32.
// ---------------------------------------------------------------------------
extern "C" void kernel_launch(void* const* d_in, const int* in_sizes, int n_in,
                              void* d_out, int out_size) {
    const float4* q   = (const float4*)d_in[0];
    const float4* k   = (const float4*)d_in[1];
    const void*   idx = d_in[2];
    float*        out = (float*)d_out;

    // K0: zero denominators
    init_sum_kernel<<<(NSEG + 255) / 256, 256>>>();

    // K1: 2 edges per warp -> E/2 warps -> E*16 threads
    {
        const long long total_threads = (long long)E_EDGES * 16;
        const int blocks = (int)((total_threads + 255) / 256);
        score_exp_kernel<<<blocks, 256>>>(q, k, idx, out);
    }

    // K2: 4 edges per thread
    {
        const int threads = E_EDGES / 4;
        normalize_kernel<<<(threads + 255) / 256, 256>>>(idx, out);
    }
}

// round 2
// speedup vs baseline: 1.0922x; 1.0922x over previous
#include <cuda_runtime.h>

// Problem constants (fixed by the reference)
#define E_EDGES   2000000
#define NSEG      100000
#define INV_TEMP  0.125f   // 1 / TEMPERATURE

// Scratch: per-segment softmax denominators. __device__ global (no allocs allowed).
__device__ float g_sum[NSEG];

// ---------------------------------------------------------------------------
// Index dtype detection: reference asks int64 but default JAX canonicalizes to
// int32. Probe 8 bytes at int64-position E/4: sorted uniform over [0,100000)
// means the mid-buffer int64 has hi-word 0; the int32 interpretation puts a
// nonzero value (~50000) there.
// ---------------------------------------------------------------------------
__device__ __forceinline__ bool index_is_64(const void* __restrict__ idx) {
    const int2 probe = __ldg(&((const int2*)idx)[E_EDGES / 4]);
    return probe.y == 0;
}

__device__ __forceinline__ int idx_at(const void* __restrict__ idx, bool is64, int i) {
    if (is64) return (int)__ldcs(&((const long long*)idx)[i]);
    else      return __ldcs(&((const int*)idx)[i]);
}

// ---------------------------------------------------------------------------
// K1: per-edge dot -> exp -> store numerator (streaming), REDG denominator.
// Half-warp (16 lanes) per edge; lane loads one float4 of q and k each
// (16 lanes x 16B = 256B = full row, perfectly coalesced).
// Grid is exact (E*16 threads), no bounds checks.
// ---------------------------------------------------------------------------
__global__ void __launch_bounds__(256)
score_exp_kernel(const float4* __restrict__ q,
                 const float4* __restrict__ k,
                 const void*   __restrict__ index,
                 float*        __restrict__ out) {
    const int tid  = blockIdx.x * blockDim.x + threadIdx.x;
    const int warp = tid >> 5;
    const int lane = tid & 31;
    const int half = lane >> 4;       // which edge within the warp
    const int sub  = lane & 15;       // lane within the 16-lane group

    const long long e = (long long)warp * 2 + half;

    // Streaming loads: q/k are touched exactly once, keep them out of L2.
    const float4 a = __ldcs(&q[e * 16 + sub]);
    const float4 b = __ldcs(&k[e * 16 + sub]);
    float d = a.x * b.x + a.y * b.y + a.z * b.z + a.w * b.w;

    // Reduce across the 16-lane group
    d += __shfl_xor_sync(0xFFFFFFFFu, d, 8);
    d += __shfl_xor_sync(0xFFFFFFFFu, d, 4);
    d += __shfl_xor_sync(0xFFFFFFFFu, d, 2);
    d += __shfl_xor_sync(0xFFFFFFFFu, d, 1);

    if (sub == 0) {
        const float ex = __expf(d * INV_TEMP);
        __stcs(&out[e], ex);

        const bool is64 = index_is_64(index);      // cached broadcast, leaders only
        const int  seg  = idx_at(index, is64, (int)e);

        // Warp-aggregate: the two edges in this warp (lanes 0 & 16) usually
        // share a segment (index is sorted). Combine into one REDG when so.
        const unsigned mask = 0x00010001u;
        const int   oseg = __shfl_xor_sync(mask, seg, 16);
        const float oex  = __shfl_xor_sync(mask, ex,  16);
        if (seg == oseg) {
            if (half == 0) atomicAdd(&g_sum[seg], ex + oex);
        } else {
            atomicAdd(&g_sum[seg], ex);
        }
    }
}

// ---------------------------------------------------------------------------
// K2: normalize. 4 edges per thread, vectorized out and (int32 path) index.
// Sorted index -> g_sum gathers hit L1/L2.
// ---------------------------------------------------------------------------
__global__ void __launch_bounds__(256)
normalize_kernel(const void* __restrict__ index,
                 float*      __restrict__ out) {
    const int t = blockIdx.x * blockDim.x + threadIdx.x;
    const int i = t * 4;
    if (i >= E_EDGES) return;

    const bool is64 = index_is_64(index);

    float4 o = __ldcs(reinterpret_cast<const float4*>(out + i));

    int s0, s1, s2, s3;
    if (!is64) {
        const int4 sv = __ldcs(reinterpret_cast<const int4*>(index) + t);
        s0 = sv.x; s1 = sv.y; s2 = sv.z; s3 = sv.w;
    } else {
        const longlong2 sa = __ldcs(reinterpret_cast<const longlong2*>(index) + t * 2);
        const longlong2 sb = __ldcs(reinterpret_cast<const longlong2*>(index) + t * 2 + 1);
        s0 = (int)sa.x; s1 = (int)sa.y; s2 = (int)sb.x; s3 = (int)sb.y;
    }

    o.x /= g_sum[s0];
    o.y /= g_sum[s1];
    o.z /= g_sum[s2];
    o.w /= g_sum[s3];
    __stcs(reinterpret_cast<float4*>(out + i), o);
}

// ---------------------------------------------------------------------------
// Launch: inputs in metadata order: q [E*64 f32], k [E*64 f32], index [E].
// Output: E f32.
// ---------------------------------------------------------------------------
extern "C" void kernel_launch(void* const* d_in, const int* in_sizes, int n_in,
                              void* d_out, int out_size) {
    const float4* q   = (const float4*)d_in[0];
    const float4* k   = (const float4*)d_in[1];
    const void*   idx = d_in[2];
    float*        out = (float*)d_out;

    // Zero denominators with a memset node (cheaper than a kernel launch).
    static float* sum_ptr = nullptr;
    if (sum_ptr == nullptr) {
        cudaGetSymbolAddress((void**)&sum_ptr, g_sum);
    }
    cudaMemsetAsync(sum_ptr, 0, NSEG * sizeof(float));

    // K1: 2 edges per warp -> E*16 threads; divides 256 exactly (125000 blocks).
    {
        const long long total_threads = (long long)E_EDGES * 16;
        const int blocks = (int)(total_threads / 256);
        score_exp_kernel<<<blocks, 256>>>(q, k, idx, out);
    }

    // K2: 4 edges per thread
    {
        const int threads = E_EDGES / 4;
        normalize_kernel<<<(threads + 255) / 256, 256>>>(idx, out);
    }
}

// round 3
// speedup vs baseline: 1.1005x; 1.0076x over previous
#include <cuda_runtime.h>

// Problem constants (fixed by the reference)
#define E_EDGES   2000000
#define NSEG      100000
#define INV_TEMP  0.125f   // 1 / TEMPERATURE

// Scratch (no allocs allowed): denominators + their reciprocals.
// g_sum is zero-initialized at module load; rcp_kernel re-zeroes it every
// call, so each kernel_launch sees zeros -> deterministic across replays.
__device__ float g_sum[NSEG];
__device__ float g_rcp[NSEG];

// ---------------------------------------------------------------------------
// Index dtype detection: reference asks int64 but default JAX canonicalizes to
// int32. Probe 8 bytes at int64-position E/4: sorted uniform over [0,100000)
// -> int64 hi-word there is 0; int32 interpretation puts ~50000 there.
// ---------------------------------------------------------------------------
__device__ __forceinline__ bool index_is_64(const void* __restrict__ idx) {
    const int2 probe = __ldg(&((const int2*)idx)[E_EDGES / 4]);
    return probe.y == 0;
}

// ---------------------------------------------------------------------------
// K1: per-edge dot -> exp -> numerator store + REDG denominator.
// Half-warp (16 lanes) per edge: 16 x float4 = 256B coalesced per row.
// Lane 0 finishes BOTH edges of its warp: one float2 store, one vector index
// load, merged atomics. Grid exact (E*16 threads), no bounds checks.
// ---------------------------------------------------------------------------
__global__ void __launch_bounds__(256)
score_exp_kernel(const float4* __restrict__ q,
                 const float4* __restrict__ k,
                 const void*   __restrict__ index,
                 float*        __restrict__ out) {
    const int tid  = blockIdx.x * blockDim.x + threadIdx.x;
    const int warp = tid >> 5;
    const int lane = tid & 31;
    const int half = lane >> 4;       // edge within warp
    const int sub  = lane & 15;       // lane within 16-group

    const long long e = (long long)warp * 2 + half;

    // Streaming loads: q/k touched exactly once, keep out of L2.
    const float4 a = __ldcs(&q[e * 16 + sub]);
    const float4 b = __ldcs(&k[e * 16 + sub]);
    float d = a.x * b.x + a.y * b.y + a.z * b.z + a.w * b.w;

    // Reduce within the 16-lane group
    d += __shfl_xor_sync(0xFFFFFFFFu, d, 8);
    d += __shfl_xor_sync(0xFFFFFFFFu, d, 4);
    d += __shfl_xor_sync(0xFFFFFFFFu, d, 2);
    d += __shfl_xor_sync(0xFFFFFFFFu, d, 1);

    // Bring the other edge's score to every lane (both halves execute this).
    const float dOther = __shfl_xor_sync(0xFFFFFFFFu, d, 16);

    if (lane == 0) {
        const float ex0 = __expf(d      * INV_TEMP);   // edge warp*2
        const float ex1 = __expf(dOther * INV_TEMP);   // edge warp*2 + 1

        // One 8B store for both numerators (out + warp*2 is 8B-aligned).
        __stcs(reinterpret_cast<float2*>(out) + warp, make_float2(ex0, ex1));

        // One vector load for both segment ids.
        int s0, s1;
        if (index_is_64(index)) {
            const longlong2 sv = __ldcs(reinterpret_cast<const longlong2*>(index) + warp);
            s0 = (int)sv.x; s1 = (int)sv.y;
        } else {
            const int2 sv = __ldcs(reinterpret_cast<const int2*>(index) + warp);
            s0 = sv.x; s1 = sv.y;
        }

        // Sorted index -> usually same segment: merge into one REDG.
        if (s0 == s1) {
            atomicAdd(&g_sum[s0], ex0 + ex1);
        } else {
            atomicAdd(&g_sum[s0], ex0);
            atomicAdd(&g_sum[s1], ex1);
        }
    }
}

// ---------------------------------------------------------------------------
// K1.5: reciprocal of denominators + self-reset of g_sum for the next replay.
// rcp.approx (2^-22) is far inside the 1e-3 tolerance. Empty segments give
// inf, which no edge ever reads. Vectorized: NSEG divisible by 4.
// ---------------------------------------------------------------------------
__global__ void __launch_bounds__(256)
rcp_kernel() {
    const int i = blockIdx.x * blockDim.x + threadIdx.x;  // 25000 threads
    if (i >= NSEG / 4) return;
    float4 s = reinterpret_cast<float4*>(g_sum)[i];
    float4 r;
    r.x = __fdividef(1.0f, s.x);
    r.y = __fdividef(1.0f, s.y);
    r.z = __fdividef(1.0f, s.z);
    r.w = __fdividef(1.0f, s.w);
    reinterpret_cast<float4*>(g_rcp)[i] = r;
    reinterpret_cast<float4*>(g_sum)[i] = make_float4(0.f, 0.f, 0.f, 0.f);
}

// ---------------------------------------------------------------------------
// K2: normalize = multiply by reciprocal. 4 edges/thread, vectorized.
// Sorted index -> g_rcp gathers hit L1 (__ldg non-coherent path).
// ---------------------------------------------------------------------------
__global__ void __launch_bounds__(256)
normalize_kernel(const void* __restrict__ index,
                 float*      __restrict__ out) {
    const int t = blockIdx.x * blockDim.x + threadIdx.x;
    const int i = t * 4;
    if (i >= E_EDGES) return;

    const bool is64 = index_is_64(index);

    float4 o = __ldcs(reinterpret_cast<const float4*>(out + i));

    int s0, s1, s2, s3;
    if (!is64) {
        const int4 sv = __ldcs(reinterpret_cast<const int4*>(index) + t);
        s0 = sv.x; s1 = sv.y; s2 = sv.z; s3 = sv.w;
    } else {
        const longlong2 sa = __ldcs(reinterpret_cast<const longlong2*>(index) + t * 2);
        const longlong2 sb = __ldcs(reinterpret_cast<const longlong2*>(index) + t * 2 + 1);
        s0 = (int)sa.x; s1 = (int)sa.y; s2 = (int)sb.x; s3 = (int)sb.y;
    }

    o.x *= __ldg(&g_rcp[s0]);
    o.y *= __ldg(&g_rcp[s1]);
    o.z *= __ldg(&g_rcp[s2]);
    o.w *= __ldg(&g_rcp[s3]);
    __stcs(reinterpret_cast<float4*>(out + i), o);
}

// ---------------------------------------------------------------------------
// Launch. Inputs in metadata order: q [E*64 f32], k [E*64 f32], index [E].
// Output: E f32. Three kernel nodes, no memset (rcp_kernel self-resets g_sum).
// ---------------------------------------------------------------------------
extern "C" void kernel_launch(void* const* d_in, const int* in_sizes, int n_in,
                              void* d_out, int out_size) {
    const float4* q   = (const float4*)d_in[0];
    const float4* k   = (const float4*)d_in[1];
    const void*   idx = d_in[2];
    float*        out = (float*)d_out;

    // K1: 2 edges per warp -> E*16 threads (divides 256 exactly: 125000 blocks)
    {
        const long long total_threads = (long long)E_EDGES * 16;
        const int blocks = (int)(total_threads / 256);
        score_exp_kernel<<<blocks, 256>>>(q, k, idx, out);
    }

    // K1.5: reciprocals + reset (25000 threads)
    rcp_kernel<<<(NSEG / 4 + 255) / 256, 256>>>();

    // K2: 4 edges per thread
    {
        const int threads = E_EDGES / 4;
        normalize_kernel<<<(threads + 255) / 256, 256>>>(idx, out);
    }
}

// round 4
// speedup vs baseline: 1.2729x; 1.1567x over previous
#include <cuda_runtime.h>

// Problem constants (fixed by the reference)
#define E_EDGES   2000000
#define NSEG      100000
#define INV_TEMP  0.125f   // 1 / TEMPERATURE

// Scratch (no allocs allowed): denominators + reciprocals.
// g_sum is zero-initialized at module load; rcp_kernel re-zeroes it every
// call, so each kernel_launch sees zeros -> deterministic across replays.
__device__ float g_sum[NSEG];
__device__ float g_rcp[NSEG];

// ---------------------------------------------------------------------------
// Index dtype detection: reference asks int64 but default JAX canonicalizes to
// int32. Probe 8 bytes at int64-position E/4: sorted uniform over [0,100000)
// -> int64 hi-word there is 0; int32 interpretation puts ~50000 there.
// ---------------------------------------------------------------------------
__device__ __forceinline__ bool index_is_64(const void* __restrict__ idx) {
    const int2 probe = __ldg(&((const int2*)idx)[E_EDGES / 4]);
    return probe.y == 0;
}

// ---------------------------------------------------------------------------
// K1: 4 edges per warp, 8 lanes per edge, 4 front-batched LDG.128 per thread
// (2 q-chunks + 2 k-chunks). Each 8-lane group covers one 256B row of q and k.
// Lane 0 finishes all 4 edges: one float4 numerator store, one int4 (or 2x
// longlong2) index load, run-merged atomics. Grid exact, no bounds checks.
// ---------------------------------------------------------------------------
__global__ void __launch_bounds__(256)
score_exp_kernel(const float4* __restrict__ q,
                 const float4* __restrict__ k,
                 const void*   __restrict__ index,
                 float*        __restrict__ out) {
    const int tid  = blockIdx.x * blockDim.x + threadIdx.x;
    const int warp = tid >> 5;
    const int lane = tid & 31;
    const int g    = lane >> 3;       // edge within warp (0..3)
    const int sub  = lane & 7;        // lane within 8-group

    const long long e    = (long long)warp * 4 + g;
    const long long base = e * 16;    // float4 index of row start

    // Front-batched independent streaming loads (MLP_p1 = 4):
    const float4 qa = __ldcs(&q[base + sub]);
    const float4 qb = __ldcs(&q[base + sub + 8]);
    const float4 ka = __ldcs(&k[base + sub]);
    const float4 kb = __ldcs(&k[base + sub + 8]);

    float d0 = qa.x * ka.x + qa.y * ka.y + qa.z * ka.z + qa.w * ka.w;
    float d1 = qb.x * kb.x + qb.y * kb.y + qb.z * kb.z + qb.w * kb.w;
    float d  = d0 + d1;

    // Reduce within the 8-lane group (3 shuffles)
    d += __shfl_xor_sync(0xFFFFFFFFu, d, 4);
    d += __shfl_xor_sync(0xFFFFFFFFu, d, 2);
    d += __shfl_xor_sync(0xFFFFFFFFu, d, 1);

    // Every lane in group g now has edge g's score; exponentiate (MUFU, cheap).
    const float ex = __expf(d * INV_TEMP);

    // Gather the 4 group results to lane 0.
    const float e1 = __shfl_sync(0xFFFFFFFFu, ex, 8);
    const float e2 = __shfl_sync(0xFFFFFFFFu, ex, 16);
    const float e3 = __shfl_sync(0xFFFFFFFFu, ex, 24);

    if (lane == 0) {
        // One 16B store for 4 numerators (out + warp*4 is 16B-aligned).
        __stcs(reinterpret_cast<float4*>(out) + warp, make_float4(ex, e1, e2, e3));

        // One vector load for 4 segment ids.
        int s0, s1, s2, s3;
        if (index_is_64(index)) {
            const longlong2 sa = __ldcs(reinterpret_cast<const longlong2*>(index) + warp * 2);
            const longlong2 sb = __ldcs(reinterpret_cast<const longlong2*>(index) + warp * 2 + 1);
            s0 = (int)sa.x; s1 = (int)sa.y; s2 = (int)sb.x; s3 = (int)sb.y;
        } else {
            const int4 sv = __ldcs(reinterpret_cast<const int4*>(index) + warp);
            s0 = sv.x; s1 = sv.y; s2 = sv.z; s3 = sv.w;
        }

        // Run-merge (index sorted -> usually one REDG per 4 edges).
        float acc = ex;
        int   cur = s0;
        if (s1 == cur) acc += e1; else { atomicAdd(&g_sum[cur], acc); cur = s1; acc = e1; }
        if (s2 == cur) acc += e2; else { atomicAdd(&g_sum[cur], acc); cur = s2; acc = e2; }
        if (s3 == cur) acc += e3; else { atomicAdd(&g_sum[cur], acc); cur = s3; acc = e3; }
        atomicAdd(&g_sum[cur], acc);
    }
}

// ---------------------------------------------------------------------------
// K1.5: reciprocal of denominators + self-reset of g_sum for the next replay.
// ---------------------------------------------------------------------------
__global__ void __launch_bounds__(256)
rcp_kernel() {
    const int i = blockIdx.x * blockDim.x + threadIdx.x;  // 25000 threads
    if (i >= NSEG / 4) return;
    float4 s = reinterpret_cast<float4*>(g_sum)[i];
    float4 r;
    r.x = __fdividef(1.0f, s.x);
    r.y = __fdividef(1.0f, s.y);
    r.z = __fdividef(1.0f, s.z);
    r.w = __fdividef(1.0f, s.w);
    reinterpret_cast<float4*>(g_rcp)[i] = r;
    reinterpret_cast<float4*>(g_sum)[i] = make_float4(0.f, 0.f, 0.f, 0.f);
}

// ---------------------------------------------------------------------------
// K2: normalize = multiply by reciprocal. 4 edges/thread, vectorized.
// ---------------------------------------------------------------------------
__global__ void __launch_bounds__(256)
normalize_kernel(const void* __restrict__ index,
                 float*      __restrict__ out) {
    const int t = blockIdx.x * blockDim.x + threadIdx.x;
    const int i = t * 4;
    if (i >= E_EDGES) return;

    const bool is64 = index_is_64(index);

    float4 o = __ldcs(reinterpret_cast<const float4*>(out + i));

    int s0, s1, s2, s3;
    if (!is64) {
        const int4 sv = __ldcs(reinterpret_cast<const int4*>(index) + t);
        s0 = sv.x; s1 = sv.y; s2 = sv.z; s3 = sv.w;
    } else {
        const longlong2 sa = __ldcs(reinterpret_cast<const longlong2*>(index) + t * 2);
        const longlong2 sb = __ldcs(reinterpret_cast<const longlong2*>(index) + t * 2 + 1);
        s0 = (int)sa.x; s1 = (int)sa.y; s2 = (int)sb.x; s3 = (int)sb.y;
    }

    o.x *= __ldg(&g_rcp[s0]);
    o.y *= __ldg(&g_rcp[s1]);
    o.z *= __ldg(&g_rcp[s2]);
    o.w *= __ldg(&g_rcp[s3]);
    __stcs(reinterpret_cast<float4*>(out + i), o);
}

// ---------------------------------------------------------------------------
// Launch. Inputs in metadata order: q [E*64 f32], k [E*64 f32], index [E].
// Output: E f32. Three kernel nodes.
// ---------------------------------------------------------------------------
extern "C" void kernel_launch(void* const* d_in, const int* in_sizes, int n_in,
                              void* d_out, int out_size) {
    const float4* q   = (const float4*)d_in[0];
    const float4* k   = (const float4*)d_in[1];
    const void*   idx = d_in[2];
    float*        out = (float*)d_out;

    // K1: 4 edges per warp -> E*8 threads (divides 256 exactly: 62500 blocks)
    {
        const long long total_threads = (long long)E_EDGES * 8;
        const int blocks = (int)(total_threads / 256);
        score_exp_kernel<<<blocks, 256>>>(q, k, idx, out);
    }

    // K1.5: reciprocals + reset (25000 threads)
    rcp_kernel<<<(NSEG / 4 + 255) / 256, 256>>>();

    // K2: 4 edges per thread
    {
        const int threads = E_EDGES / 4;
        normalize_kernel<<<(threads + 255) / 256, 256>>>(idx, out);
    }
}